// round 15
// baseline (speedup 1.0000x reference)
#include <cuda_runtime.h>
#include <math.h>

#define BB   4
#define TT   250
#define NS   100
#define DEP  64
#define SS   64000
#define NROW (BB*TT*NS)      // 100000 frame-rows
#define NSEQ (BB*NS)         // 400 scan sequences
#define L3N  8000            // level-3 scan length per sequence
#define NSPLIT 4
#define NPER (NS/NSPLIT)     // 25 sinusoids per partial

typedef unsigned long long u64;

__device__ float g_freq[NROW];
__device__ float g_amp[NROW];
__device__ float g_scan3[(size_t)NSEQ * L3N];            // 12.8 MB

// ---------------- packed f32x2 helpers (per-lane IEEE rn) -------------------
__device__ __forceinline__ u64 pk2(float lo, float hi) {
    u64 r; asm("mov.b64 %0,{%1,%2};" : "=l"(r) : "f"(lo), "f"(hi)); return r;
}
__device__ __forceinline__ void up2(u64 v, float& lo, float& hi) {
    asm("mov.b64 {%0,%1},%2;" : "=f"(lo), "=f"(hi) : "l"(v));
}
__device__ __forceinline__ u64 fma2_(u64 a, u64 b, u64 c) {
    u64 d; asm("fma.rn.f32x2 %0,%1,%2,%3;" : "=l"(d) : "l"(a), "l"(b), "l"(c)); return d;
}
__device__ __forceinline__ u64 mul2_(u64 a, u64 b) {
    u64 d; asm("mul.rn.f32x2 %0,%1,%2;" : "=l"(d) : "l"(a), "l"(b)); return d;
}
__device__ __forceinline__ u64 add2_(u64 a, u64 b) {
    u64 d; asm("add.rn.f32x2 %0,%1,%2;" : "=l"(d) : "l"(a), "l"(b)); return d;
}
#define NEG1_2 0xBF800000BF800000ULL
__device__ __forceinline__ u64 sub2_(u64 x, u64 y) {
    u64 d; asm("fma.rn.f32x2 %0,%1,%2,%3;" : "=l"(d)
               : "l"(y), "l"((u64)NEG1_2), "l"(x)); return d;
}

// packed sin via MUFU: 2-step Cody-Waite mod pi with magic-number rounding,
// parity sign folded into r, then MUFU.SIN on |r|<=pi/2 (validated R14).
__device__ __forceinline__ u64 sin2mu(u64 x) {
    const float INVPI = (float)(1.0 / 3.14159265358979323846);
    const double PID = 3.14159265358979323846;
    const float H1 = (float)PID;
    const float H2 = (float)(PID - (double)H1);
    const u64 BIG2 = 0x4B4000004B400000ULL;          // 1.5 * 2^23 packed

    u64 t  = mul2_(x, pk2(INVPI, INVPI));
    u64 tb = add2_(t, BIG2);
    u64 q  = sub2_(tb, BIG2);                        // == rint(t), exact
    u64 r  = fma2_(q, pk2(-H1, -H1), x);
    r = fma2_(q, pk2(-H2, -H2), r);
    u64 mask = (tb & 0x0000000100000001ULL) << 31;   // parity(q) per lane
    r ^= mask;
    float rl, rh; up2(r, rl, rh);
    return pk2(__sinf(rl), __sinf(rh));              // MUFU.SIN x2
}

// ---------------------------------------------------------------------------
// controls: TWO threads per row. Each thread covers 32 contiguous logits
// (16 packed df iterations); row max via fmaxf+shfl (order-invariant);
// df partials combined in double after a pair shuffle (~1e-13 class, same
// as the validated R13 regrouping). 33KB smem / 256 threads -> ~75% occ.
// ---------------------------------------------------------------------------
__global__ void __launch_bounds__(256) ctrl_kernel(
        const float* __restrict__ logits,
        const float* __restrict__ amp_in) {
    __shared__ float sx[256 * 33];               // stride-33: conflict-free
    __shared__ u64 binsh[DEP / 2], binsl[DEP / 2];

    int tid  = threadIdx.x;
    int rbase = blockIdx.x * 128;

    if (tid < DEP / 2) {
        double bd0 = (double)(2 * tid)     / 63.0;
        double bd1 = (double)(2 * tid + 1) / 63.0;
        float bh0 = (float)bd0, bl0 = (float)(bd0 - (double)bh0);
        float bh1 = (float)bd1, bl1 = (float)(bd1 - (double)bh1);
        binsh[tid] = pk2(bh0, bh1);
        binsl[tid] = pk2(bl0, bl1);
    }

    // coalesced stage: block covers 128 rows x 64 logits
    int nrows = NROW - rbase; if (nrows > 128) nrows = 128;
    int nelem = nrows * DEP;
    const float* src = logits + (size_t)rbase * DEP;
    for (int i = tid; i < nelem; i += 256) {
        int r = i >> 6, c = i & 63;
        sx[(2 * r + (c >> 5)) * 33 + (c & 31)] = src[i];
    }
    __syncthreads();

    int row  = rbase + (tid >> 1);
    if (row >= NROW) return;                     // warp-aligned exits
    int half = tid & 1;                          // 0: j 0..31, 1: j 32..63
    const float* x = sx + tid * 33;

    float m = x[0];
    #pragma unroll
    for (int j = 1; j < 32; ++j) m = fmaxf(m, x[j]);
    m = fmaxf(m, __shfl_xor_sync(0xffffffffu, m, 1));   // full-row max

    const u64 zero2 = pk2(0.f, 0.f);
    u64 seh = zero2, sel = zero2, sbh = zero2, sbl = zero2;

    int jj0 = half * 16;
    #pragma unroll 4
    for (int i = 0; i < 16; ++i) {
        float e0 = expf(__fsub_rn(x[2 * i],     m));
        float e1 = expf(__fsub_rn(x[2 * i + 1], m));
        u64 e2 = pk2(e0, e1);

        u64 s  = add2_(seh, e2);
        u64 bv = sub2_(s, seh);
        u64 er = add2_(sub2_(seh, sub2_(s, bv)), sub2_(e2, bv));
        u64 lo = add2_(sel, er);
        seh = add2_(s, lo);
        sel = sub2_(lo, sub2_(seh, s));

        u64 bh = binsh[jj0 + i], bl = binsl[jj0 + i];
        u64 ph = mul2_(e2, bh);
        u64 pl = fma2_(e2, bh, ph ^ 0x8000000080000000ULL);
        pl = fma2_(e2, bl, pl);

        s  = add2_(sbh, ph);
        bv = sub2_(s, sbh);
        er = add2_(sub2_(sbh, sub2_(s, bv)), sub2_(ph, bv));
        lo = add2_(add2_(sbl, er), pl);
        sbh = add2_(s, lo);
        sbl = sub2_(lo, sub2_(sbh, s));
    }

    float sh0, sh1, sl0, sl1, bh0, bh1, bl0, bl1;
    up2(seh, sh0, sh1); up2(sel, sl0, sl1);
    up2(sbh, bh0, bh1); up2(sbl, bl0, bl1);
    double pse = ((double)sh0 + (double)sl0) + ((double)sh1 + (double)sl1);
    double psb = ((double)bh0 + (double)bl0) + ((double)bh1 + (double)bl1);
    double ose = __shfl_xor_sync(0xffffffffu, pse, 1);
    double osb = __shfl_xor_sync(0xffffffffu, psb, 1);
    double se  = pse + ose;                      // commutative: same both lanes
    double seb = psb + osb;
    float fu = (float)(seb / se);

    const float mminf = (float)15.48682057635244;
    const float mdelf = (float)103.72627427729668;
    float midi = __fadd_rn(mminf, __fmul_rn(fu, mdelf));
    float ex   = __fdiv_rn(__fsub_rn(midi, 69.0f), 12.0f);
    float hz   = __fmul_rn(440.0f, powf(2.0f, ex));

    if (half == 0) {
        g_freq[row] = hz;
    } else {
        float xv = amp_in[row];
        float sg = __fdiv_rn(1.0f, __fadd_rn(1.0f, expf(-xv)));
        float p  = powf(sg, (float)2.302585092994046);
        float a  = __fadd_rn(__fmul_rn(2.0f, p), 1e-7f);
        if (!(hz < 8000.0f)) a = 0.0f;
        g_amp[row] = a;
    }
}

// ---------------------------------------------------------------------------
// scan: unchanged from R13/R14 (level-3 inclusive scan, bit-exact packed build).
// ---------------------------------------------------------------------------
__global__ void __launch_bounds__(1024) scan_kernel() {
    extern __shared__ float sm[];            // 15994 level floats + fr[251]
    float* fr = sm + 15994;

    int seq = blockIdx.x;
    int b = seq / NS, n = seq % NS;
    int tid = threadIdx.x;

    for (int t = tid; t < TT; t += 1024)
        fr[t] = g_freq[(b * TT + t) * NS + n];
    __syncthreads();
    if (tid == 0) fr[TT] = fr[TT - 1];
    __syncthreads();

    const u64 c256v  = pk2(0.00390625f, 0.00390625f);
    const u64 one2   = pk2(1.0f, 1.0f);
    const float C2PI = (float)(6.283185307179586 / 16000.0);
    const u64 c2piv  = pk2(C2PI, C2PI);

    for (int i = tid; i < L3N; i += 1024) {
        int s = 8 * i;
        int k = s >> 8, r = s & 255;
        float x0 = fr[k], x1 = fr[k + 1];
        u64 x0v = pk2(x0, x0), x1v = pk2(x1, x1);

        float rf0 = (float)r;
        u64 rv01 = pk2(rf0,        rf0 + 1.f);
        u64 rv23 = pk2(rf0 + 2.f,  rf0 + 3.f);
        u64 rv45 = pk2(rf0 + 4.f,  rf0 + 5.f);
        u64 rv67 = pk2(rf0 + 6.f,  rf0 + 7.f);

        u64 fv, ov, fe;
        float o0,o1,o2,o3,o4,o5,o6,o7;
        fv = mul2_(rv01, c256v); ov = fma2_(fv, (u64)NEG1_2, one2);
        fe = add2_(mul2_(x0v, ov), mul2_(x1v, fv));
        up2(mul2_(fe, c2piv), o0, o1);
        fv = mul2_(rv23, c256v); ov = fma2_(fv, (u64)NEG1_2, one2);
        fe = add2_(mul2_(x0v, ov), mul2_(x1v, fv));
        up2(mul2_(fe, c2piv), o2, o3);
        fv = mul2_(rv45, c256v); ov = fma2_(fv, (u64)NEG1_2, one2);
        fe = add2_(mul2_(x0v, ov), mul2_(x1v, fv));
        up2(mul2_(fe, c2piv), o4, o5);
        fv = mul2_(rv67, c256v); ov = fma2_(fv, (u64)NEG1_2, one2);
        fe = add2_(mul2_(x0v, ov), mul2_(x1v, fv));
        up2(mul2_(fe, c2piv), o6, o7);

        float a20 = __fadd_rn(__fadd_rn(o0, o1), __fadd_rn(o2, o3));
        float a21 = __fadd_rn(__fadd_rn(o4, o5), __fadd_rn(o6, o7));
        sm[i] = __fadd_rn(a20, a21);
    }
    __syncthreads();

    int offs[13], szs[13];
    {
        int o = 0, s = L3N;
        #pragma unroll
        for (int l = 0; l < 13; ++l) { offs[l] = o; szs[l] = s; o += s; s >>= 1; }
    }

    for (int l = 0; l < 12; ++l) {
        const float* srcp = sm + offs[l];
        float*       dst  = sm + offs[l + 1];
        int m = szs[l + 1];
        for (int i = tid; i < m; i += 1024)
            dst[i] = __fadd_rn(srcp[2 * i], srcp[2 * i + 1]);
        __syncthreads();
    }

    for (int l = 11; l >= 0; --l) {
        float*       a  = sm + offs[l];
        const float* sc = sm + offs[l + 1];
        int nl = szs[l];
        for (int j = tid; j < nl; j += 1024) {
            float v;
            if (j & 1)        v = sc[j >> 1];
            else if (j == 0)  v = a[0];
            else              v = __fadd_rn(sc[(j >> 1) - 1], a[j]);
            a[j] = v;
        }
        __syncthreads();
    }

    float* g = g_scan3 + (size_t)seq * L3N;
    for (int i = tid; i < L3N; i += 1024) g[i] = sm[i];
}

// ---------------------------------------------------------------------------
// FUSED output + combine: unchanged from R14 (validated).
// ---------------------------------------------------------------------------
__global__ void __launch_bounds__(256) out_kernel(float* __restrict__ out) {
    int bx = blockIdx.x;              // frames 2bx, 2bx+1  (bx < 125)
    int b  = blockIdx.y;
    int t  = threadIdx.x;

    __shared__ float fs[3 * NS], as[3 * NS];
    __shared__ float red[4 * 64 * 9];            // stride-9 pad: conflict-free

    for (int i = t; i < 3 * NS; i += 256) {
        int fl = i / NS, nn = i % NS;
        int frame = 2 * bx + fl;
        if (frame > TT - 1) frame = TT - 1;
        fs[i] = g_freq[(b * TT + frame) * NS + nn];
        as[i] = g_amp [(b * TT + frame) * NS + nn];
    }
    __syncthreads();

    int sp  = t >> 6;                 // n-split 0..3
    int c   = t & 63;                 // cell within block
    int fid = c >> 5, j = c & 31;
    int k   = 2 * bx + fid;           // frame (< 250 always)
    int r0  = 8 * j;
    int i3  = k * 32 + j;             // scan3 index

    float w_[8], ow_[8];
    #pragma unroll
    for (int i = 0; i < 8; ++i) {
        float rf = (float)(r0 + i);
        float warg = __fdiv_rn(__fmul_rn((float)3.141592653589793, rf), 256.0f);
        w_[i]  = __fsub_rn(0.5f, __fmul_rn(0.5f, cosf(warg)));
        ow_[i] = __fsub_rn(1.0f, w_[i]);
    }
    u64 wv[4], owv[4], rv[4];
    #pragma unroll
    for (int i = 0; i < 4; ++i) {
        wv[i]  = pk2(w_[2*i],  w_[2*i+1]);
        owv[i] = pk2(ow_[2*i], ow_[2*i+1]);
        rv[i]  = pk2((float)(r0 + 2*i), (float)(r0 + 2*i + 1));
    }
    const float C2PI    = (float)(6.283185307179586 / 16000.0);
    const float C2PI256 = (float)(6.283185307179586 / 16000.0 / 256.0);

    const float* fp0 = fs + fid * NS;
    const float* fp1 = fs + (fid + 1) * NS;
    const float* ap0 = as + fid * NS;
    const float* ap1 = as + (fid + 1) * NS;

    int nb = sp * NPER;
    const float* buf = g_scan3 + ((size_t)(b * NS + nb)) * L3N + i3;

    u64 acc[4];
    acc[0] = acc[1] = acc[2] = acc[3] = pk2(0.f, 0.f);

    #pragma unroll 2
    for (int m = 0; m < NPER; ++m) {
        int n = nb + m;
        float f0 = fp0[n], f1 = fp1[n];
        float A  = __fmul_rn(f0, C2PI);
        float D  = __fmul_rn(__fsub_rn(f1, f0), C2PI256);
        u64 Av = pk2(A, A), Dv = pk2(D, D);

        u64 o01 = fma2_(rv[0], Dv, Av);
        u64 o23 = fma2_(rv[1], Dv, Av);
        u64 o45 = fma2_(rv[2], Dv, Av);
        u64 o67 = fma2_(rv[3], Dv, Av);

        float o0, o1, o2, o3, o4, o5, o6, o7u;
        up2(o01, o0, o1); up2(o23, o2, o3);
        up2(o45, o4, o5); up2(o67, o6, o7u);

        float t01 = __fadd_rn(o0, o1);
        float a20 = __fadd_rn(t01, __fadd_rn(o2, o3));
        float t45 = __fadd_rn(o4, o5);

        float bq = buf[(size_t)m * L3N];
        float bm = (i3 > 0) ? buf[(size_t)m * L3N - 1] : 0.0f;

        float P0 = __fadd_rn(bm, o0);
        float P1 = __fadd_rn(bm, t01);
        float P2 = __fadd_rn(P1, o2);
        float P3 = __fadd_rn(bm, a20);
        float P4 = __fadd_rn(P3, o4);
        float P5 = __fadd_rn(P3, t45);
        float P6 = __fadd_rn(P5, o6);
        float P7 = bq;

        u64 s01 = sin2mu(pk2(P0, P1));
        u64 s23 = sin2mu(pk2(P2, P3));
        u64 s45 = sin2mu(pk2(P4, P5));
        u64 s67 = sin2mu(pk2(P6, P7));

        float a0 = ap0[n], a1 = ap1[n];
        u64 a0v = pk2(a0, a0), a1v = pk2(a1, a1);
        u64 ae01 = fma2_(a1v, wv[0], mul2_(a0v, owv[0]));
        u64 ae23 = fma2_(a1v, wv[1], mul2_(a0v, owv[1]));
        u64 ae45 = fma2_(a1v, wv[2], mul2_(a0v, owv[2]));
        u64 ae67 = fma2_(a1v, wv[3], mul2_(a0v, owv[3]));

        acc[0] = fma2_(ae01, s01, acc[0]);
        acc[1] = fma2_(ae23, s23, acc[1]);
        acc[2] = fma2_(ae45, s45, acc[2]);
        acc[3] = fma2_(ae67, s67, acc[3]);
    }

    {
        float* rb = red + (sp * 64 + c) * 9;
        float lo, hi;
        up2(acc[0], lo, hi); rb[0] = lo; rb[1] = hi;
        up2(acc[1], lo, hi); rb[2] = lo; rb[3] = hi;
        up2(acc[2], lo, hi); rb[4] = lo; rb[5] = hi;
        up2(acc[3], lo, hi); rb[6] = lo; rb[7] = hi;
    }
    __syncthreads();

    #pragma unroll
    for (int ss = t; ss < 512; ss += 256) {
        int cc = ss >> 3, ii = ss & 7;
        float v = __fadd_rn(__fadd_rn(__fadd_rn(
                      red[(0 * 64 + cc) * 9 + ii],
                      red[(1 * 64 + cc) * 9 + ii]),
                      red[(2 * 64 + cc) * 9 + ii]),
                      red[(3 * 64 + cc) * 9 + ii]);
        out[b * SS + bx * 512 + ss] = v;
    }
}

// ---------------------------------------------------------------------------
extern "C" void kernel_launch(void* const* d_in, const int* in_sizes, int n_in,
                              void* d_out, int out_size) {
    const float* amps  = (const float*)d_in[0];   // [4,250,100]
    const float* freqs = (const float*)d_in[1];   // [4,250,6400]
    if (n_in >= 2 && in_sizes[0] > in_sizes[1]) {
        const float* t = amps; amps = freqs; freqs = t;
    }

    static const size_t scan_smem = (15994 + 256) * sizeof(float);  // ~65 KB
    cudaFuncSetAttribute(scan_kernel,
                         cudaFuncAttributeMaxDynamicSharedMemorySize,
                         (int)scan_smem);

    ctrl_kernel<<<(NROW + 127) / 128, 256>>>(freqs, amps);
    scan_kernel<<<NSEQ, 1024, scan_smem>>>();
    out_kernel<<<dim3(TT / 2, BB), 256>>>((float*)d_out);
}

// round 16
// speedup vs baseline: 1.0651x; 1.0651x over previous
#include <cuda_runtime.h>
#include <math.h>

#define BB   4
#define TT   250
#define NS   100
#define DEP  64
#define SS   64000
#define NROW (BB*TT*NS)      // 100000 frame-rows
#define NSEQ (BB*NS)         // 400 scan sequences
#define L3N  8000            // level-3 scan length per sequence
#define NSPLIT 4
#define NPER (NS/NSPLIT)     // 25 sinusoids per partial
#define CTRL_ROWS 128

typedef unsigned long long u64;

__device__ float g_freq[NROW];
__device__ float g_amp[NROW];
__device__ float g_scan3[(size_t)NSEQ * L3N];            // 12.8 MB

// ---------------- packed f32x2 helpers (per-lane IEEE rn) -------------------
__device__ __forceinline__ u64 pk2(float lo, float hi) {
    u64 r; asm("mov.b64 %0,{%1,%2};" : "=l"(r) : "f"(lo), "f"(hi)); return r;
}
__device__ __forceinline__ void up2(u64 v, float& lo, float& hi) {
    asm("mov.b64 {%0,%1},%2;" : "=f"(lo), "=f"(hi) : "l"(v));
}
__device__ __forceinline__ u64 fma2_(u64 a, u64 b, u64 c) {
    u64 d; asm("fma.rn.f32x2 %0,%1,%2,%3;" : "=l"(d) : "l"(a), "l"(b), "l"(c)); return d;
}
__device__ __forceinline__ u64 mul2_(u64 a, u64 b) {
    u64 d; asm("mul.rn.f32x2 %0,%1,%2;" : "=l"(d) : "l"(a), "l"(b)); return d;
}
__device__ __forceinline__ u64 add2_(u64 a, u64 b) {
    u64 d; asm("add.rn.f32x2 %0,%1,%2;" : "=l"(d) : "l"(a), "l"(b)); return d;
}
#define NEG1_2 0xBF800000BF800000ULL
__device__ __forceinline__ u64 sub2_(u64 x, u64 y) {
    u64 d; asm("fma.rn.f32x2 %0,%1,%2,%3;" : "=l"(d)
               : "l"(y), "l"((u64)NEG1_2), "l"(x)); return d;
}

// packed sin via MUFU: 2-step Cody-Waite mod pi with magic-number rounding,
// parity sign folded into r, then MUFU.SIN on |r|<=pi/2 (validated R14).
__device__ __forceinline__ u64 sin2mu(u64 x) {
    const float INVPI = (float)(1.0 / 3.14159265358979323846);
    const double PID = 3.14159265358979323846;
    const float H1 = (float)PID;
    const float H2 = (float)(PID - (double)H1);
    const u64 BIG2 = 0x4B4000004B400000ULL;          // 1.5 * 2^23 packed

    u64 t  = mul2_(x, pk2(INVPI, INVPI));
    u64 tb = add2_(t, BIG2);
    u64 q  = sub2_(tb, BIG2);                        // == rint(t), exact
    u64 r  = fma2_(q, pk2(-H1, -H1), x);
    r = fma2_(q, pk2(-H2, -H2), r);
    u64 mask = (tb & 0x0000000100000001ULL) << 31;   // parity(q) per lane
    r ^= mask;
    float rl, rh; up2(r, rl, rh);
    return pk2(__sinf(rl), __sinf(rh));              // MUFU.SIN x2
}

// df TwoSum accumulate: (hi,lo) += e   (per-lane IEEE, packed)
#define DF_ADD(hi, lo_, e) do {                                            \
    u64 _s  = add2_(hi, e);                                                \
    u64 _bv = sub2_(_s, hi);                                               \
    u64 _er = add2_(sub2_(hi, sub2_(_s, _bv)), sub2_((e), _bv));           \
    u64 _lo = add2_(lo_, _er);                                             \
    hi  = add2_(_s, _lo);                                                  \
    lo_ = sub2_(_lo, sub2_(hi, _s));                                       \
} while (0)

// df TwoSum accumulate with extra low term: (hi,lo) += (ph, pl)
#define DF_ADD2(hi, lo_, ph, pl) do {                                      \
    u64 _s  = add2_(hi, ph);                                               \
    u64 _bv = sub2_(_s, hi);                                               \
    u64 _er = add2_(sub2_(hi, sub2_(_s, _bv)), sub2_((ph), _bv));          \
    u64 _lo = add2_(add2_(lo_, _er), (pl));                                \
    hi  = add2_(_s, _lo);                                                  \
    lo_ = sub2_(_lo, sub2_(hi, _s));                                       \
} while (0)

// ---------------------------------------------------------------------------
// controls: one THREAD per row (R14 structure), but TWO independent df
// accumulator sets (A: pairs 0..15, B: pairs 16..31) interleaved -> serial
// chain halves, ILP 2->4, no duplicated tail. A/B combined in double (same
// regrouping class validated in R13/R15).
// ---------------------------------------------------------------------------
__global__ void __launch_bounds__(CTRL_ROWS) ctrl_kernel(
        const float* __restrict__ logits,
        const float* __restrict__ amp_in) {
    __shared__ float sx[CTRL_ROWS * 65];
    __shared__ u64 binsh[DEP / 2], binsl[DEP / 2];

    int tid  = threadIdx.x;
    int base = blockIdx.x * CTRL_ROWS;
    int row  = base + tid;

    if (tid < DEP / 2) {
        double bd0 = (double)(2 * tid)     / 63.0;
        double bd1 = (double)(2 * tid + 1) / 63.0;
        float bh0 = (float)bd0, bl0 = (float)(bd0 - (double)bh0);
        float bh1 = (float)bd1, bl1 = (float)(bd1 - (double)bh1);
        binsh[tid] = pk2(bh0, bh1);
        binsl[tid] = pk2(bl0, bl1);
    }

    int nrows = NROW - base; if (nrows > CTRL_ROWS) nrows = CTRL_ROWS;
    int nelem = nrows * DEP;
    const float* src = logits + (size_t)base * DEP;
    for (int i = tid; i < nelem; i += CTRL_ROWS)
        sx[(i >> 6) * 65 + (i & 63)] = src[i];
    __syncthreads();

    if (row >= NROW) return;
    const float* x = sx + tid * 65;

    float m = x[0];
    #pragma unroll
    for (int j = 1; j < DEP; ++j) m = fmaxf(m, x[j]);

    const u64 zero2 = pk2(0.f, 0.f);
    u64 sehA = zero2, selA = zero2, sbhA = zero2, sblA = zero2;
    u64 sehB = zero2, selB = zero2, sbhB = zero2, sblB = zero2;

    #pragma unroll 4
    for (int i = 0; i < 16; ++i) {
        // stream A: pair i (elements 2i, 2i+1)
        {
            float e0 = expf(__fsub_rn(x[2 * i],     m));
            float e1 = expf(__fsub_rn(x[2 * i + 1], m));
            u64 e2 = pk2(e0, e1);
            DF_ADD(sehA, selA, e2);
            u64 bh = binsh[i], bl = binsl[i];
            u64 ph = mul2_(e2, bh);
            u64 pl = fma2_(e2, bh, ph ^ 0x8000000080000000ULL);
            pl = fma2_(e2, bl, pl);
            DF_ADD2(sbhA, sblA, ph, pl);
        }
        // stream B: pair i+16 (elements 32+2i, 32+2i+1)
        {
            float e0 = expf(__fsub_rn(x[32 + 2 * i],     m));
            float e1 = expf(__fsub_rn(x[32 + 2 * i + 1], m));
            u64 e2 = pk2(e0, e1);
            DF_ADD(sehB, selB, e2);
            u64 bh = binsh[16 + i], bl = binsl[16 + i];
            u64 ph = mul2_(e2, bh);
            u64 pl = fma2_(e2, bh, ph ^ 0x8000000080000000ULL);
            pl = fma2_(e2, bl, pl);
            DF_ADD2(sbhB, sblB, ph, pl);
        }
    }

    float h0, h1, l0, l1;
    double se, seb;
    up2(sehA, h0, h1); up2(selA, l0, l1);
    se  = ((double)h0 + (double)l0) + ((double)h1 + (double)l1);
    up2(sehB, h0, h1); up2(selB, l0, l1);
    se += ((double)h0 + (double)l0) + ((double)h1 + (double)l1);
    up2(sbhA, h0, h1); up2(sblA, l0, l1);
    seb  = ((double)h0 + (double)l0) + ((double)h1 + (double)l1);
    up2(sbhB, h0, h1); up2(sblB, l0, l1);
    seb += ((double)h0 + (double)l0) + ((double)h1 + (double)l1);
    float fu = (float)(seb / se);

    const float mminf = (float)15.48682057635244;
    const float mdelf = (float)103.72627427729668;
    float midi = __fadd_rn(mminf, __fmul_rn(fu, mdelf));
    float ex   = __fdiv_rn(__fsub_rn(midi, 69.0f), 12.0f);
    float hz   = __fmul_rn(440.0f, powf(2.0f, ex));
    g_freq[row] = hz;

    float xv = amp_in[row];
    float sg = __fdiv_rn(1.0f, __fadd_rn(1.0f, expf(-xv)));
    float p  = powf(sg, (float)2.302585092994046);
    float a  = __fadd_rn(__fmul_rn(2.0f, p), 1e-7f);
    if (!(hz < 8000.0f)) a = 0.0f;
    g_amp[row] = a;
}

// ---------------------------------------------------------------------------
// scan: unchanged from R13/R14 (level-3 inclusive scan, bit-exact packed build).
// ---------------------------------------------------------------------------
__global__ void __launch_bounds__(1024) scan_kernel() {
    extern __shared__ float sm[];            // 15994 level floats + fr[251]
    float* fr = sm + 15994;

    int seq = blockIdx.x;
    int b = seq / NS, n = seq % NS;
    int tid = threadIdx.x;

    for (int t = tid; t < TT; t += 1024)
        fr[t] = g_freq[(b * TT + t) * NS + n];
    __syncthreads();
    if (tid == 0) fr[TT] = fr[TT - 1];
    __syncthreads();

    const u64 c256v  = pk2(0.00390625f, 0.00390625f);
    const u64 one2   = pk2(1.0f, 1.0f);
    const float C2PI = (float)(6.283185307179586 / 16000.0);
    const u64 c2piv  = pk2(C2PI, C2PI);

    for (int i = tid; i < L3N; i += 1024) {
        int s = 8 * i;
        int k = s >> 8, r = s & 255;
        float x0 = fr[k], x1 = fr[k + 1];
        u64 x0v = pk2(x0, x0), x1v = pk2(x1, x1);

        float rf0 = (float)r;
        u64 rv01 = pk2(rf0,        rf0 + 1.f);
        u64 rv23 = pk2(rf0 + 2.f,  rf0 + 3.f);
        u64 rv45 = pk2(rf0 + 4.f,  rf0 + 5.f);
        u64 rv67 = pk2(rf0 + 6.f,  rf0 + 7.f);

        u64 fv, ov, fe;
        float o0,o1,o2,o3,o4,o5,o6,o7;
        fv = mul2_(rv01, c256v); ov = fma2_(fv, (u64)NEG1_2, one2);
        fe = add2_(mul2_(x0v, ov), mul2_(x1v, fv));
        up2(mul2_(fe, c2piv), o0, o1);
        fv = mul2_(rv23, c256v); ov = fma2_(fv, (u64)NEG1_2, one2);
        fe = add2_(mul2_(x0v, ov), mul2_(x1v, fv));
        up2(mul2_(fe, c2piv), o2, o3);
        fv = mul2_(rv45, c256v); ov = fma2_(fv, (u64)NEG1_2, one2);
        fe = add2_(mul2_(x0v, ov), mul2_(x1v, fv));
        up2(mul2_(fe, c2piv), o4, o5);
        fv = mul2_(rv67, c256v); ov = fma2_(fv, (u64)NEG1_2, one2);
        fe = add2_(mul2_(x0v, ov), mul2_(x1v, fv));
        up2(mul2_(fe, c2piv), o6, o7);

        float a20 = __fadd_rn(__fadd_rn(o0, o1), __fadd_rn(o2, o3));
        float a21 = __fadd_rn(__fadd_rn(o4, o5), __fadd_rn(o6, o7));
        sm[i] = __fadd_rn(a20, a21);
    }
    __syncthreads();

    int offs[13], szs[13];
    {
        int o = 0, s = L3N;
        #pragma unroll
        for (int l = 0; l < 13; ++l) { offs[l] = o; szs[l] = s; o += s; s >>= 1; }
    }

    for (int l = 0; l < 12; ++l) {
        const float* srcp = sm + offs[l];
        float*       dst  = sm + offs[l + 1];
        int m = szs[l + 1];
        for (int i = tid; i < m; i += 1024)
            dst[i] = __fadd_rn(srcp[2 * i], srcp[2 * i + 1]);
        __syncthreads();
    }

    for (int l = 11; l >= 0; --l) {
        float*       a  = sm + offs[l];
        const float* sc = sm + offs[l + 1];
        int nl = szs[l];
        for (int j = tid; j < nl; j += 1024) {
            float v;
            if (j & 1)        v = sc[j >> 1];
            else if (j == 0)  v = a[0];
            else              v = __fadd_rn(sc[(j >> 1) - 1], a[j]);
            a[j] = v;
        }
        __syncthreads();
    }

    float* g = g_scan3 + (size_t)seq * L3N;
    for (int i = tid; i < L3N; i += 1024) g[i] = sm[i];
}

// ---------------------------------------------------------------------------
// FUSED output + combine: unchanged from R14 (validated).
// ---------------------------------------------------------------------------
__global__ void __launch_bounds__(256) out_kernel(float* __restrict__ out) {
    int bx = blockIdx.x;              // frames 2bx, 2bx+1  (bx < 125)
    int b  = blockIdx.y;
    int t  = threadIdx.x;

    __shared__ float fs[3 * NS], as[3 * NS];
    __shared__ float red[4 * 64 * 9];            // stride-9 pad: conflict-free

    for (int i = t; i < 3 * NS; i += 256) {
        int fl = i / NS, nn = i % NS;
        int frame = 2 * bx + fl;
        if (frame > TT - 1) frame = TT - 1;
        fs[i] = g_freq[(b * TT + frame) * NS + nn];
        as[i] = g_amp [(b * TT + frame) * NS + nn];
    }
    __syncthreads();

    int sp  = t >> 6;                 // n-split 0..3
    int c   = t & 63;                 // cell within block
    int fid = c >> 5, j = c & 31;
    int k   = 2 * bx + fid;           // frame (< 250 always)
    int r0  = 8 * j;
    int i3  = k * 32 + j;             // scan3 index

    float w_[8], ow_[8];
    #pragma unroll
    for (int i = 0; i < 8; ++i) {
        float rf = (float)(r0 + i);
        float warg = __fdiv_rn(__fmul_rn((float)3.141592653589793, rf), 256.0f);
        w_[i]  = __fsub_rn(0.5f, __fmul_rn(0.5f, cosf(warg)));
        ow_[i] = __fsub_rn(1.0f, w_[i]);
    }
    u64 wv[4], owv[4], rv[4];
    #pragma unroll
    for (int i = 0; i < 4; ++i) {
        wv[i]  = pk2(w_[2*i],  w_[2*i+1]);
        owv[i] = pk2(ow_[2*i], ow_[2*i+1]);
        rv[i]  = pk2((float)(r0 + 2*i), (float)(r0 + 2*i + 1));
    }
    const float C2PI    = (float)(6.283185307179586 / 16000.0);
    const float C2PI256 = (float)(6.283185307179586 / 16000.0 / 256.0);

    const float* fp0 = fs + fid * NS;
    const float* fp1 = fs + (fid + 1) * NS;
    const float* ap0 = as + fid * NS;
    const float* ap1 = as + (fid + 1) * NS;

    int nb = sp * NPER;
    const float* buf = g_scan3 + ((size_t)(b * NS + nb)) * L3N + i3;

    u64 acc[4];
    acc[0] = acc[1] = acc[2] = acc[3] = pk2(0.f, 0.f);

    #pragma unroll 2
    for (int m = 0; m < NPER; ++m) {
        int n = nb + m;
        float f0 = fp0[n], f1 = fp1[n];
        float A  = __fmul_rn(f0, C2PI);
        float D  = __fmul_rn(__fsub_rn(f1, f0), C2PI256);
        u64 Av = pk2(A, A), Dv = pk2(D, D);

        u64 o01 = fma2_(rv[0], Dv, Av);
        u64 o23 = fma2_(rv[1], Dv, Av);
        u64 o45 = fma2_(rv[2], Dv, Av);
        u64 o67 = fma2_(rv[3], Dv, Av);

        float o0, o1, o2, o3, o4, o5, o6, o7u;
        up2(o01, o0, o1); up2(o23, o2, o3);
        up2(o45, o4, o5); up2(o67, o6, o7u);

        float t01 = __fadd_rn(o0, o1);
        float a20 = __fadd_rn(t01, __fadd_rn(o2, o3));
        float t45 = __fadd_rn(o4, o5);

        float bq = buf[(size_t)m * L3N];
        float bm = (i3 > 0) ? buf[(size_t)m * L3N - 1] : 0.0f;

        float P0 = __fadd_rn(bm, o0);
        float P1 = __fadd_rn(bm, t01);
        float P2 = __fadd_rn(P1, o2);
        float P3 = __fadd_rn(bm, a20);
        float P4 = __fadd_rn(P3, o4);
        float P5 = __fadd_rn(P3, t45);
        float P6 = __fadd_rn(P5, o6);
        float P7 = bq;

        u64 s01 = sin2mu(pk2(P0, P1));
        u64 s23 = sin2mu(pk2(P2, P3));
        u64 s45 = sin2mu(pk2(P4, P5));
        u64 s67 = sin2mu(pk2(P6, P7));

        float a0 = ap0[n], a1 = ap1[n];
        u64 a0v = pk2(a0, a0), a1v = pk2(a1, a1);
        u64 ae01 = fma2_(a1v, wv[0], mul2_(a0v, owv[0]));
        u64 ae23 = fma2_(a1v, wv[1], mul2_(a0v, owv[1]));
        u64 ae45 = fma2_(a1v, wv[2], mul2_(a0v, owv[2]));
        u64 ae67 = fma2_(a1v, wv[3], mul2_(a0v, owv[3]));

        acc[0] = fma2_(ae01, s01, acc[0]);
        acc[1] = fma2_(ae23, s23, acc[1]);
        acc[2] = fma2_(ae45, s45, acc[2]);
        acc[3] = fma2_(ae67, s67, acc[3]);
    }

    {
        float* rb = red + (sp * 64 + c) * 9;
        float lo, hi;
        up2(acc[0], lo, hi); rb[0] = lo; rb[1] = hi;
        up2(acc[1], lo, hi); rb[2] = lo; rb[3] = hi;
        up2(acc[2], lo, hi); rb[4] = lo; rb[5] = hi;
        up2(acc[3], lo, hi); rb[6] = lo; rb[7] = hi;
    }
    __syncthreads();

    #pragma unroll
    for (int ss = t; ss < 512; ss += 256) {
        int cc = ss >> 3, ii = ss & 7;
        float v = __fadd_rn(__fadd_rn(__fadd_rn(
                      red[(0 * 64 + cc) * 9 + ii],
                      red[(1 * 64 + cc) * 9 + ii]),
                      red[(2 * 64 + cc) * 9 + ii]),
                      red[(3 * 64 + cc) * 9 + ii]);
        out[b * SS + bx * 512 + ss] = v;
    }
}

// ---------------------------------------------------------------------------
extern "C" void kernel_launch(void* const* d_in, const int* in_sizes, int n_in,
                              void* d_out, int out_size) {
    const float* amps  = (const float*)d_in[0];   // [4,250,100]
    const float* freqs = (const float*)d_in[1];   // [4,250,6400]
    if (n_in >= 2 && in_sizes[0] > in_sizes[1]) {
        const float* t = amps; amps = freqs; freqs = t;
    }

    static const size_t scan_smem = (15994 + 256) * sizeof(float);  // ~65 KB
    cudaFuncSetAttribute(scan_kernel,
                         cudaFuncAttributeMaxDynamicSharedMemorySize,
                         (int)scan_smem);

    ctrl_kernel<<<(NROW + CTRL_ROWS - 1) / CTRL_ROWS, CTRL_ROWS>>>(freqs, amps);
    scan_kernel<<<NSEQ, 1024, scan_smem>>>();
    out_kernel<<<dim3(TT / 2, BB), 256>>>((float*)d_out);
}

// round 17
// speedup vs baseline: 1.1188x; 1.0504x over previous
#include <cuda_runtime.h>
#include <math.h>

#define BB   4
#define TT   250
#define NS   100
#define DEP  64
#define SS   64000
#define NROW (BB*TT*NS)      // 100000 frame-rows
#define NSEQ (BB*NS)         // 400 scan sequences
#define L3N  8000            // level-3 scan length per sequence
#define NSPLIT 4
#define NPER (NS/NSPLIT)     // 25 sinusoids per partial
#define CTRL_ROWS 128

typedef unsigned long long u64;

__device__ float g_freq[NROW];
__device__ float g_amp[NROW];
__device__ float g_scan3[(size_t)NSEQ * L3N];            // 12.8 MB

// ---------------- packed f32x2 helpers (per-lane IEEE rn) -------------------
__device__ __forceinline__ u64 pk2(float lo, float hi) {
    u64 r; asm("mov.b64 %0,{%1,%2};" : "=l"(r) : "f"(lo), "f"(hi)); return r;
}
__device__ __forceinline__ void up2(u64 v, float& lo, float& hi) {
    asm("mov.b64 {%0,%1},%2;" : "=f"(lo), "=f"(hi) : "l"(v));
}
__device__ __forceinline__ u64 fma2_(u64 a, u64 b, u64 c) {
    u64 d; asm("fma.rn.f32x2 %0,%1,%2,%3;" : "=l"(d) : "l"(a), "l"(b), "l"(c)); return d;
}
__device__ __forceinline__ u64 mul2_(u64 a, u64 b) {
    u64 d; asm("mul.rn.f32x2 %0,%1,%2;" : "=l"(d) : "l"(a), "l"(b)); return d;
}
__device__ __forceinline__ u64 add2_(u64 a, u64 b) {
    u64 d; asm("add.rn.f32x2 %0,%1,%2;" : "=l"(d) : "l"(a), "l"(b)); return d;
}
#define NEG1_2 0xBF800000BF800000ULL
__device__ __forceinline__ u64 sub2_(u64 x, u64 y) {
    u64 d; asm("fma.rn.f32x2 %0,%1,%2,%3;" : "=l"(d)
               : "l"(y), "l"((u64)NEG1_2), "l"(x)); return d;
}

// packed sin via MUFU: 2-step Cody-Waite mod pi with magic-number rounding,
// parity sign folded into r, then MUFU.SIN on |r|<=pi/2 (validated R14).
__device__ __forceinline__ u64 sin2mu(u64 x) {
    const float INVPI = (float)(1.0 / 3.14159265358979323846);
    const double PID = 3.14159265358979323846;
    const float H1 = (float)PID;
    const float H2 = (float)(PID - (double)H1);
    const u64 BIG2 = 0x4B4000004B400000ULL;          // 1.5 * 2^23 packed

    u64 t  = mul2_(x, pk2(INVPI, INVPI));
    u64 tb = add2_(t, BIG2);
    u64 q  = sub2_(tb, BIG2);                        // == rint(t), exact
    u64 r  = fma2_(q, pk2(-H1, -H1), x);
    r = fma2_(q, pk2(-H2, -H2), r);
    u64 mask = (tb & 0x0000000100000001ULL) << 31;   // parity(q) per lane
    r ^= mask;
    float rl, rh; up2(r, rl, rh);
    return pk2(__sinf(rl), __sinf(rh));              // MUFU.SIN x2
}

// ---------------------------------------------------------------------------
// controls: R14 numerics (validated: rel_err 8.09623e-4) with float4 staging,
// fully unrolled -> 16 LDG.128 in flight per thread (was 64 serial LDG.32).
// ---------------------------------------------------------------------------
__global__ void __launch_bounds__(CTRL_ROWS) ctrl_kernel(
        const float* __restrict__ logits,
        const float* __restrict__ amp_in) {
    __shared__ float sx[CTRL_ROWS * 65];
    __shared__ u64 binsh[DEP / 2], binsl[DEP / 2];

    int tid  = threadIdx.x;
    int base = blockIdx.x * CTRL_ROWS;
    int row  = base + tid;

    if (tid < DEP / 2) {
        double bd0 = (double)(2 * tid)     / 63.0;
        double bd1 = (double)(2 * tid + 1) / 63.0;
        float bh0 = (float)bd0, bl0 = (float)(bd0 - (double)bh0);
        float bh1 = (float)bd1, bl1 = (float)(bd1 - (double)bh1);
        binsh[tid] = pk2(bh0, bh1);
        binsl[tid] = pk2(bl0, bl1);
    }

    int nrows = NROW - base; if (nrows > CTRL_ROWS) nrows = CTRL_ROWS;
    const float4* src4 = (const float4*)(logits + (size_t)base * DEP);

    if (nrows == CTRL_ROWS) {
        // main path: 128 rows * 16 float4 = 2048 float4s; 16 per thread, all
        // loads issued back-to-back (full unroll) for maximum MLP.
        float4 v[16];
        #pragma unroll
        for (int kq = 0; kq < 16; ++kq) v[kq] = src4[tid + kq * CTRL_ROWS];
        #pragma unroll
        for (int kq = 0; kq < 16; ++kq) {
            int e = (tid + kq * CTRL_ROWS) * 4;
            float* d = &sx[(e >> 6) * 65 + (e & 63)];
            d[0] = v[kq].x; d[1] = v[kq].y; d[2] = v[kq].z; d[3] = v[kq].w;
        }
    } else {
        int n4 = nrows * (DEP / 4);
        for (int i = tid; i < n4; i += CTRL_ROWS) {
            float4 v = src4[i];
            int e = i * 4;
            float* d = &sx[(e >> 6) * 65 + (e & 63)];
            d[0] = v.x; d[1] = v.y; d[2] = v.z; d[3] = v.w;
        }
    }
    __syncthreads();

    if (row >= NROW) return;
    const float* x = sx + tid * 65;

    float m = x[0];
    #pragma unroll
    for (int j = 1; j < DEP; ++j) m = fmaxf(m, x[j]);

    const u64 zero2 = pk2(0.f, 0.f);
    u64 seh = zero2, sel = zero2, sbh = zero2, sbl = zero2;

    #pragma unroll 8
    for (int jj = 0; jj < DEP / 2; ++jj) {
        float e0 = expf(__fsub_rn(x[2 * jj],     m));
        float e1 = expf(__fsub_rn(x[2 * jj + 1], m));
        u64 e2 = pk2(e0, e1);

        u64 s  = add2_(seh, e2);
        u64 bv = sub2_(s, seh);
        u64 er = add2_(sub2_(seh, sub2_(s, bv)), sub2_(e2, bv));
        u64 lo = add2_(sel, er);
        seh = add2_(s, lo);
        sel = sub2_(lo, sub2_(seh, s));

        u64 bh = binsh[jj], bl = binsl[jj];
        u64 ph = mul2_(e2, bh);
        u64 pl = fma2_(e2, bh, ph ^ 0x8000000080000000ULL);
        pl = fma2_(e2, bl, pl);

        s  = add2_(sbh, ph);
        bv = sub2_(s, sbh);
        er = add2_(sub2_(sbh, sub2_(s, bv)), sub2_(ph, bv));
        lo = add2_(add2_(sbl, er), pl);
        sbh = add2_(s, lo);
        sbl = sub2_(lo, sub2_(sbh, s));
    }

    float sh0, sh1, sl0, sl1, bh0, bh1, bl0, bl1;
    up2(seh, sh0, sh1); up2(sel, sl0, sl1);
    up2(sbh, bh0, bh1); up2(sbl, bl0, bl1);
    double se  = ((double)sh0 + (double)sl0) + ((double)sh1 + (double)sl1);
    double seb = ((double)bh0 + (double)bl0) + ((double)bh1 + (double)bl1);
    float fu = (float)(seb / se);

    const float mminf = (float)15.48682057635244;
    const float mdelf = (float)103.72627427729668;
    float midi = __fadd_rn(mminf, __fmul_rn(fu, mdelf));
    float ex   = __fdiv_rn(__fsub_rn(midi, 69.0f), 12.0f);
    float hz   = __fmul_rn(440.0f, powf(2.0f, ex));
    g_freq[row] = hz;

    float xv = amp_in[row];
    float sg = __fdiv_rn(1.0f, __fadd_rn(1.0f, expf(-xv)));
    float p  = powf(sg, (float)2.302585092994046);
    float a  = __fadd_rn(__fmul_rn(2.0f, p), 1e-7f);
    if (!(hz < 8000.0f)) a = 0.0f;
    g_amp[row] = a;
}

// ---------------------------------------------------------------------------
// scan: unchanged from R13/R14 (level-3 inclusive scan, bit-exact packed build).
// ---------------------------------------------------------------------------
__global__ void __launch_bounds__(1024) scan_kernel() {
    extern __shared__ float sm[];            // 15994 level floats + fr[251]
    float* fr = sm + 15994;

    int seq = blockIdx.x;
    int b = seq / NS, n = seq % NS;
    int tid = threadIdx.x;

    for (int t = tid; t < TT; t += 1024)
        fr[t] = g_freq[(b * TT + t) * NS + n];
    __syncthreads();
    if (tid == 0) fr[TT] = fr[TT - 1];
    __syncthreads();

    const u64 c256v  = pk2(0.00390625f, 0.00390625f);
    const u64 one2   = pk2(1.0f, 1.0f);
    const float C2PI = (float)(6.283185307179586 / 16000.0);
    const u64 c2piv  = pk2(C2PI, C2PI);

    for (int i = tid; i < L3N; i += 1024) {
        int s = 8 * i;
        int k = s >> 8, r = s & 255;
        float x0 = fr[k], x1 = fr[k + 1];
        u64 x0v = pk2(x0, x0), x1v = pk2(x1, x1);

        float rf0 = (float)r;
        u64 rv01 = pk2(rf0,        rf0 + 1.f);
        u64 rv23 = pk2(rf0 + 2.f,  rf0 + 3.f);
        u64 rv45 = pk2(rf0 + 4.f,  rf0 + 5.f);
        u64 rv67 = pk2(rf0 + 6.f,  rf0 + 7.f);

        u64 fv, ov, fe;
        float o0,o1,o2,o3,o4,o5,o6,o7;
        fv = mul2_(rv01, c256v); ov = fma2_(fv, (u64)NEG1_2, one2);
        fe = add2_(mul2_(x0v, ov), mul2_(x1v, fv));
        up2(mul2_(fe, c2piv), o0, o1);
        fv = mul2_(rv23, c256v); ov = fma2_(fv, (u64)NEG1_2, one2);
        fe = add2_(mul2_(x0v, ov), mul2_(x1v, fv));
        up2(mul2_(fe, c2piv), o2, o3);
        fv = mul2_(rv45, c256v); ov = fma2_(fv, (u64)NEG1_2, one2);
        fe = add2_(mul2_(x0v, ov), mul2_(x1v, fv));
        up2(mul2_(fe, c2piv), o4, o5);
        fv = mul2_(rv67, c256v); ov = fma2_(fv, (u64)NEG1_2, one2);
        fe = add2_(mul2_(x0v, ov), mul2_(x1v, fv));
        up2(mul2_(fe, c2piv), o6, o7);

        float a20 = __fadd_rn(__fadd_rn(o0, o1), __fadd_rn(o2, o3));
        float a21 = __fadd_rn(__fadd_rn(o4, o5), __fadd_rn(o6, o7));
        sm[i] = __fadd_rn(a20, a21);
    }
    __syncthreads();

    int offs[13], szs[13];
    {
        int o = 0, s = L3N;
        #pragma unroll
        for (int l = 0; l < 13; ++l) { offs[l] = o; szs[l] = s; o += s; s >>= 1; }
    }

    for (int l = 0; l < 12; ++l) {
        const float* srcp = sm + offs[l];
        float*       dst  = sm + offs[l + 1];
        int m = szs[l + 1];
        for (int i = tid; i < m; i += 1024)
            dst[i] = __fadd_rn(srcp[2 * i], srcp[2 * i + 1]);
        __syncthreads();
    }

    for (int l = 11; l >= 0; --l) {
        float*       a  = sm + offs[l];
        const float* sc = sm + offs[l + 1];
        int nl = szs[l];
        for (int j = tid; j < nl; j += 1024) {
            float v;
            if (j & 1)        v = sc[j >> 1];
            else if (j == 0)  v = a[0];
            else              v = __fadd_rn(sc[(j >> 1) - 1], a[j]);
            a[j] = v;
        }
        __syncthreads();
    }

    float* g = g_scan3 + (size_t)seq * L3N;
    for (int i = tid; i < L3N; i += 1024) g[i] = sm[i];
}

// ---------------------------------------------------------------------------
// FUSED output + combine: R14 structure; inner loop unroll 2 -> 5 for MLP on
// the g_scan3 loads (acc chain order per accumulator unchanged -> bit-exact).
// ---------------------------------------------------------------------------
__global__ void __launch_bounds__(256) out_kernel(float* __restrict__ out) {
    int bx = blockIdx.x;              // frames 2bx, 2bx+1  (bx < 125)
    int b  = blockIdx.y;
    int t  = threadIdx.x;

    __shared__ float fs[3 * NS], as[3 * NS];
    __shared__ float red[4 * 64 * 9];            // stride-9 pad: conflict-free

    for (int i = t; i < 3 * NS; i += 256) {
        int fl = i / NS, nn = i % NS;
        int frame = 2 * bx + fl;
        if (frame > TT - 1) frame = TT - 1;
        fs[i] = g_freq[(b * TT + frame) * NS + nn];
        as[i] = g_amp [(b * TT + frame) * NS + nn];
    }
    __syncthreads();

    int sp  = t >> 6;                 // n-split 0..3
    int c   = t & 63;                 // cell within block
    int fid = c >> 5, j = c & 31;
    int k   = 2 * bx + fid;           // frame (< 250 always)
    int r0  = 8 * j;
    int i3  = k * 32 + j;             // scan3 index

    float w_[8], ow_[8];
    #pragma unroll
    for (int i = 0; i < 8; ++i) {
        float rf = (float)(r0 + i);
        float warg = __fdiv_rn(__fmul_rn((float)3.141592653589793, rf), 256.0f);
        w_[i]  = __fsub_rn(0.5f, __fmul_rn(0.5f, cosf(warg)));
        ow_[i] = __fsub_rn(1.0f, w_[i]);
    }
    u64 wv[4], owv[4], rv[4];
    #pragma unroll
    for (int i = 0; i < 4; ++i) {
        wv[i]  = pk2(w_[2*i],  w_[2*i+1]);
        owv[i] = pk2(ow_[2*i], ow_[2*i+1]);
        rv[i]  = pk2((float)(r0 + 2*i), (float)(r0 + 2*i + 1));
    }
    const float C2PI    = (float)(6.283185307179586 / 16000.0);
    const float C2PI256 = (float)(6.283185307179586 / 16000.0 / 256.0);

    const float* fp0 = fs + fid * NS;
    const float* fp1 = fs + (fid + 1) * NS;
    const float* ap0 = as + fid * NS;
    const float* ap1 = as + (fid + 1) * NS;

    int nb = sp * NPER;
    const float* buf = g_scan3 + ((size_t)(b * NS + nb)) * L3N + i3;

    u64 acc[4];
    acc[0] = acc[1] = acc[2] = acc[3] = pk2(0.f, 0.f);

    #pragma unroll 5
    for (int m = 0; m < NPER; ++m) {
        int n = nb + m;
        float f0 = fp0[n], f1 = fp1[n];
        float A  = __fmul_rn(f0, C2PI);
        float D  = __fmul_rn(__fsub_rn(f1, f0), C2PI256);
        u64 Av = pk2(A, A), Dv = pk2(D, D);

        u64 o01 = fma2_(rv[0], Dv, Av);
        u64 o23 = fma2_(rv[1], Dv, Av);
        u64 o45 = fma2_(rv[2], Dv, Av);
        u64 o67 = fma2_(rv[3], Dv, Av);

        float o0, o1, o2, o3, o4, o5, o6, o7u;
        up2(o01, o0, o1); up2(o23, o2, o3);
        up2(o45, o4, o5); up2(o67, o6, o7u);

        float t01 = __fadd_rn(o0, o1);
        float a20 = __fadd_rn(t01, __fadd_rn(o2, o3));
        float t45 = __fadd_rn(o4, o5);

        float bq = buf[(size_t)m * L3N];
        float bm = (i3 > 0) ? buf[(size_t)m * L3N - 1] : 0.0f;

        float P0 = __fadd_rn(bm, o0);
        float P1 = __fadd_rn(bm, t01);
        float P2 = __fadd_rn(P1, o2);
        float P3 = __fadd_rn(bm, a20);
        float P4 = __fadd_rn(P3, o4);
        float P5 = __fadd_rn(P3, t45);
        float P6 = __fadd_rn(P5, o6);
        float P7 = bq;

        u64 s01 = sin2mu(pk2(P0, P1));
        u64 s23 = sin2mu(pk2(P2, P3));
        u64 s45 = sin2mu(pk2(P4, P5));
        u64 s67 = sin2mu(pk2(P6, P7));

        float a0 = ap0[n], a1 = ap1[n];
        u64 a0v = pk2(a0, a0), a1v = pk2(a1, a1);
        u64 ae01 = fma2_(a1v, wv[0], mul2_(a0v, owv[0]));
        u64 ae23 = fma2_(a1v, wv[1], mul2_(a0v, owv[1]));
        u64 ae45 = fma2_(a1v, wv[2], mul2_(a0v, owv[2]));
        u64 ae67 = fma2_(a1v, wv[3], mul2_(a0v, owv[3]));

        acc[0] = fma2_(ae01, s01, acc[0]);
        acc[1] = fma2_(ae23, s23, acc[1]);
        acc[2] = fma2_(ae45, s45, acc[2]);
        acc[3] = fma2_(ae67, s67, acc[3]);
    }

    {
        float* rb = red + (sp * 64 + c) * 9;
        float lo, hi;
        up2(acc[0], lo, hi); rb[0] = lo; rb[1] = hi;
        up2(acc[1], lo, hi); rb[2] = lo; rb[3] = hi;
        up2(acc[2], lo, hi); rb[4] = lo; rb[5] = hi;
        up2(acc[3], lo, hi); rb[6] = lo; rb[7] = hi;
    }
    __syncthreads();

    #pragma unroll
    for (int ss = t; ss < 512; ss += 256) {
        int cc = ss >> 3, ii = ss & 7;
        float v = __fadd_rn(__fadd_rn(__fadd_rn(
                      red[(0 * 64 + cc) * 9 + ii],
                      red[(1 * 64 + cc) * 9 + ii]),
                      red[(2 * 64 + cc) * 9 + ii]),
                      red[(3 * 64 + cc) * 9 + ii]);
        out[b * SS + bx * 512 + ss] = v;
    }
}

// ---------------------------------------------------------------------------
extern "C" void kernel_launch(void* const* d_in, const int* in_sizes, int n_in,
                              void* d_out, int out_size) {
    const float* amps  = (const float*)d_in[0];   // [4,250,100]
    const float* freqs = (const float*)d_in[1];   // [4,250,6400]
    if (n_in >= 2 && in_sizes[0] > in_sizes[1]) {
        const float* t = amps; amps = freqs; freqs = t;
    }

    static const size_t scan_smem = (15994 + 256) * sizeof(float);  // ~65 KB
    cudaFuncSetAttribute(scan_kernel,
                         cudaFuncAttributeMaxDynamicSharedMemorySize,
                         (int)scan_smem);

    ctrl_kernel<<<(NROW + CTRL_ROWS - 1) / CTRL_ROWS, CTRL_ROWS>>>(freqs, amps);
    scan_kernel<<<NSEQ, 1024, scan_smem>>>();
    out_kernel<<<dim3(TT / 2, BB), 256>>>((float*)d_out);
}